// round 3
// baseline (speedup 1.0000x reference)
#include <cuda_runtime.h>
#include <cuda_bf16.h>

#define KC 16
#define DD 16
#define NQUAD 136          // i<=j pairs
#define NFEAT 152          // 136 quad + 16 linear

__device__ float g_coef[NFEAT * KC];   // [feature][cluster]
__device__ float g_const[KC];

// ---------------------------------------------------------------------------
// f32x2 packed helpers
// ---------------------------------------------------------------------------
__device__ __forceinline__ unsigned long long f2pack(float lo, float hi) {
    unsigned long long r;
    asm("mov.b64 %0, {%1, %2};" : "=l"(r) : "f"(lo), "f"(hi));
    return r;
}
__device__ __forceinline__ unsigned long long f2mul(unsigned long long a, unsigned long long b) {
    unsigned long long r;
    asm("mul.rn.f32x2 %0, %1, %2;" : "=l"(r) : "l"(a), "l"(b));
    return r;
}
__device__ __forceinline__ unsigned long long f2fma(unsigned long long a, unsigned long long b,
                                                    unsigned long long c) {
    unsigned long long r;
    asm("fma.rn.f32x2 %0, %1, %2, %3;" : "=l"(r) : "l"(a), "l"(b), "l"(c));
    return r;
}
__device__ __forceinline__ void f2unpack(unsigned long long v, float& lo, float& hi) {
    asm("mov.b64 {%0, %1}, %2;" : "=f"(lo), "=f"(hi) : "l"(v));
}

// ---------------------------------------------------------------------------
// Precompute: one warp per cluster; Gauss-Jordan inverse, logdet, b = P*mu.
// ---------------------------------------------------------------------------
__global__ void gmm_precompute(const float* __restrict__ pi,
                               const float* __restrict__ mu,
                               const float* __restrict__ Sigma) {
    const int w    = threadIdx.x >> 5;
    const int lane = threadIdx.x & 31;
    const int j    = lane & 15;

    float a[16], inv[16];
#pragma unroll
    for (int i = 0; i < 16; ++i) {
        a[i]   = Sigma[w * 256 + i * 16 + j];
        inv[i] = (i == j) ? 1.0f : 0.0f;
    }

    float logdet = 0.0f;
#pragma unroll
    for (int k = 0; k < 16; ++k) {
        float piv = __shfl_sync(0xffffffffu, a[k], k);
        logdet += logf(piv);
        float ip = 1.0f / piv;
        a[k]   *= ip;
        inv[k] *= ip;
#pragma unroll
        for (int i = 0; i < 16; ++i) {
            if (i != k) {
                float m = __shfl_sync(0xffffffffu, a[i], k);
                a[i]   = fmaf(-m, a[k],   a[i]);
                inv[i] = fmaf(-m, inv[k], inv[i]);
            }
        }
    }

    const float mu_j = mu[w * 16 + j];
    float bv[16];
#pragma unroll
    for (int i = 0; i < 16; ++i) {
        float v = inv[i] * mu_j;
        v += __shfl_xor_sync(0xffffffffu, v, 8);
        v += __shfl_xor_sync(0xffffffffu, v, 4);
        v += __shfl_xor_sync(0xffffffffu, v, 2);
        v += __shfl_xor_sync(0xffffffffu, v, 1);
        bv[i] = v;
    }
    float muPmu = 0.0f;
#pragma unroll
    for (int i = 0; i < 16; ++i) muPmu += bv[i] * mu[w * 16 + i];

    if (lane < 16) {
#pragma unroll
        for (int i = 0; i < 16; ++i) {
            if (i <= j) {
                float c = (i == j ? -0.5f : -1.0f) * inv[i];
                g_coef[(j * (j + 1) / 2 + i) * KC + w] = c;
            }
        }
    }
    if (lane == 0) {
#pragma unroll
        for (int i = 0; i < 16; ++i) g_coef[(NQUAD + i) * KC + w] = bv[i];
        g_const[w] = logf(pi[w]) - 0.5f * logdet - 8.0f * 1.8378770664093453f - 0.5f * muPmu;
    }
}

// ---------------------------------------------------------------------------
// softmax + float4 store for one point's 16 logits
// ---------------------------------------------------------------------------
__device__ __forceinline__ void softmax_store(const float* l, float* outp) {
    float mx = l[0];
#pragma unroll
    for (int k = 1; k < 16; ++k) mx = fmaxf(mx, l[k]);
    float e[16], s = 0.0f;
#pragma unroll
    for (int k = 0; k < 16; ++k) { e[k] = __expf(l[k] - mx); s += e[k]; }
    float r = __fdividef(1.0f, s);
    float4* o = reinterpret_cast<float4*>(outp);
    o[0] = make_float4(e[0] * r,  e[1] * r,  e[2] * r,  e[3] * r);
    o[1] = make_float4(e[4] * r,  e[5] * r,  e[6] * r,  e[7] * r);
    o[2] = make_float4(e[8] * r,  e[9] * r,  e[10] * r, e[11] * r);
    o[3] = make_float4(e[12] * r, e[13] * r, e[14] * r, e[15] * r);
}

// ---------------------------------------------------------------------------
// Main kernel: 4 points per thread as two point-packed f32x2 pairs.
// acc[pair][k] packs (ptEven, ptOdd) for cluster k; coefficients live in smem
// pre-duplicated (c,c), so one ulonglong2 LDS (2 clusters) feeds 4 f2fma
// (2 pairs x 2 clusters). Per feature: 2 f2mul + 32 f2fma + 8 LDS.128 for
// 4 points -> FMA:LDS issue ratio ~4.2:1 with zero dup-movs in the hot loop.
// ---------------------------------------------------------------------------
__global__ void __launch_bounds__(128, 3) gmm_main(const float* __restrict__ x,
                                                   float* __restrict__ out, int n) {
    __shared__ __align__(16) unsigned long long s_coef[NFEAT * KC];  // (c,c) per [feat][k]
    __shared__ __align__(16) unsigned long long s_const[KC];

    for (int idx = threadIdx.x; idx < NFEAT * KC; idx += blockDim.x) {
        float c = g_coef[idx];
        s_coef[idx] = f2pack(c, c);
    }
    if (threadIdx.x < KC) {
        float c = g_const[threadIdx.x];
        s_const[threadIdx.x] = f2pack(c, c);
    }
    __syncthreads();

    long long t  = (long long)blockIdx.x * blockDim.x + threadIdx.x;
    long long n0 = 4 * t;
    if (n0 >= n) return;
    long long i1 = (n0 + 1 < n) ? n0 + 1 : n0;
    long long i2 = (n0 + 2 < n) ? n0 + 2 : n0;
    long long i3 = (n0 + 3 < n) ? n0 + 3 : n0;

    const float4* x0 = reinterpret_cast<const float4*>(x + n0 * DD);
    const float4* x1 = reinterpret_cast<const float4*>(x + i1 * DD);
    const float4* x2 = reinterpret_cast<const float4*>(x + i2 * DD);
    const float4* x3 = reinterpret_cast<const float4*>(x + i3 * DD);

    // point-packed X: X1 = (pt0, pt1), X2 = (pt2, pt3)
    unsigned long long X1[16], X2[16];
#pragma unroll
    for (int q = 0; q < 4; ++q) {
        float4 a = x0[q], b = x1[q], c = x2[q], d = x3[q];
        X1[4 * q + 0] = f2pack(a.x, b.x); X1[4 * q + 1] = f2pack(a.y, b.y);
        X1[4 * q + 2] = f2pack(a.z, b.z); X1[4 * q + 3] = f2pack(a.w, b.w);
        X2[4 * q + 0] = f2pack(c.x, d.x); X2[4 * q + 1] = f2pack(c.y, d.y);
        X2[4 * q + 2] = f2pack(c.z, d.z); X2[4 * q + 3] = f2pack(c.w, d.w);
    }

    unsigned long long acc1[16], acc2[16];
#pragma unroll
    for (int k = 0; k < 16; ++k) { acc1[k] = s_const[k]; acc2[k] = s_const[k]; }

    // quadratic features (i<=j), feature p = j*(j+1)/2 + i
    int p = 0;
#pragma unroll
    for (int j = 0; j < 16; ++j) {
#pragma unroll
        for (int i = 0; i <= j; ++i) {
            unsigned long long f1 = f2mul(X1[i], X1[j]);
            unsigned long long f2 = f2mul(X2[i], X2[j]);
            const ulonglong2* cp = reinterpret_cast<const ulonglong2*>(s_coef + p * KC);
#pragma unroll
            for (int m = 0; m < 8; ++m) {
                ulonglong2 cc = cp[m];                 // clusters 2m, 2m+1 (dup'd)
                acc1[2 * m]     = f2fma(cc.x, f1, acc1[2 * m]);
                acc1[2 * m + 1] = f2fma(cc.y, f1, acc1[2 * m + 1]);
                acc2[2 * m]     = f2fma(cc.x, f2, acc2[2 * m]);
                acc2[2 * m + 1] = f2fma(cc.y, f2, acc2[2 * m + 1]);
            }
            ++p;
        }
    }
    // linear features: multiplier is X itself (already point-packed)
#pragma unroll
    for (int i = 0; i < 16; ++i) {
        const ulonglong2* cp = reinterpret_cast<const ulonglong2*>(s_coef + (NQUAD + i) * KC);
#pragma unroll
        for (int m = 0; m < 8; ++m) {
            ulonglong2 cc = cp[m];
            acc1[2 * m]     = f2fma(cc.x, X1[i], acc1[2 * m]);
            acc1[2 * m + 1] = f2fma(cc.y, X1[i], acc1[2 * m + 1]);
            acc2[2 * m]     = f2fma(cc.x, X2[i], acc2[2 * m]);
            acc2[2 * m + 1] = f2fma(cc.y, X2[i], acc2[2 * m + 1]);
        }
    }

    // unpack logits: l0/l1 from acc1, l2/l3 from acc2
    float l0[16], l1[16], l2[16], l3[16];
#pragma unroll
    for (int k = 0; k < 16; ++k) {
        f2unpack(acc1[k], l0[k], l1[k]);
        f2unpack(acc2[k], l2[k], l3[k]);
    }

    softmax_store(l0, out + n0 * KC);
    if (n0 + 1 < n) softmax_store(l1, out + (n0 + 1) * KC);
    if (n0 + 2 < n) softmax_store(l2, out + (n0 + 2) * KC);
    if (n0 + 3 < n) softmax_store(l3, out + (n0 + 3) * KC);
}

extern "C" void kernel_launch(void* const* d_in, const int* in_sizes, int n_in,
                              void* d_out, int out_size) {
    const float* x     = (const float*)d_in[0];
    const float* pi    = (const float*)d_in[1];
    const float* mu    = (const float*)d_in[2];
    const float* Sigma = (const float*)d_in[3];
    float* out = (float*)d_out;

    int n = in_sizes[0] / DD;

    gmm_precompute<<<1, 512>>>(pi, mu, Sigma);

    int nthreads = (n + 3) / 4;          // 4 points per thread
    int block = 128;
    int grid  = (nthreads + block - 1) / block;
    gmm_main<<<grid, block>>>(x, out, n);
}

// round 4
// speedup vs baseline: 1.2745x; 1.2745x over previous
#include <cuda_runtime.h>
#include <cuda_bf16.h>

#define KC 16
#define DD 16
#define NQUAD 136          // i<=j pairs
#define NFEAT 152          // 136 quad + 16 linear

__device__ float g_coef[NFEAT * KC];   // [feature][cluster]
__device__ float g_const[KC];

// ---------------------------------------------------------------------------
// f32x2 packed helpers
// ---------------------------------------------------------------------------
__device__ __forceinline__ unsigned long long f2dup(float v) {
    unsigned long long r;
    asm("mov.b64 %0, {%1, %1};" : "=l"(r) : "f"(v));
    return r;
}
__device__ __forceinline__ unsigned long long f2fma(unsigned long long a, unsigned long long b,
                                                    unsigned long long c) {
    unsigned long long r;
    asm("fma.rn.f32x2 %0, %1, %2, %3;" : "=l"(r) : "l"(a), "l"(b), "l"(c));
    return r;
}
__device__ __forceinline__ void f2unpack(unsigned long long v, float& lo, float& hi) {
    asm("mov.b64 {%0, %1}, %2;" : "=f"(lo), "=f"(hi) : "l"(v));
}

// ---------------------------------------------------------------------------
// Precompute: one warp per cluster; Gauss-Jordan inverse, logdet, b = P*mu.
// ---------------------------------------------------------------------------
__global__ void gmm_precompute(const float* __restrict__ pi,
                               const float* __restrict__ mu,
                               const float* __restrict__ Sigma) {
    const int w    = threadIdx.x >> 5;
    const int lane = threadIdx.x & 31;
    const int j    = lane & 15;

    float a[16], inv[16];
#pragma unroll
    for (int i = 0; i < 16; ++i) {
        a[i]   = Sigma[w * 256 + i * 16 + j];
        inv[i] = (i == j) ? 1.0f : 0.0f;
    }

    float logdet = 0.0f;
#pragma unroll
    for (int k = 0; k < 16; ++k) {
        float piv = __shfl_sync(0xffffffffu, a[k], k);
        logdet += logf(piv);
        float ip = 1.0f / piv;
        a[k]   *= ip;
        inv[k] *= ip;
#pragma unroll
        for (int i = 0; i < 16; ++i) {
            if (i != k) {
                float m = __shfl_sync(0xffffffffu, a[i], k);
                a[i]   = fmaf(-m, a[k],   a[i]);
                inv[i] = fmaf(-m, inv[k], inv[i]);
            }
        }
    }

    const float mu_j = mu[w * 16 + j];
    float bv[16];
#pragma unroll
    for (int i = 0; i < 16; ++i) {
        float v = inv[i] * mu_j;
        v += __shfl_xor_sync(0xffffffffu, v, 8);
        v += __shfl_xor_sync(0xffffffffu, v, 4);
        v += __shfl_xor_sync(0xffffffffu, v, 2);
        v += __shfl_xor_sync(0xffffffffu, v, 1);
        bv[i] = v;
    }
    float muPmu = 0.0f;
#pragma unroll
    for (int i = 0; i < 16; ++i) muPmu += bv[i] * mu[w * 16 + i];

    if (lane < 16) {
#pragma unroll
        for (int i = 0; i < 16; ++i) {
            if (i <= j) {
                float c = (i == j ? -0.5f : -1.0f) * inv[i];
                g_coef[(j * (j + 1) / 2 + i) * KC + w] = c;
            }
        }
    }
    if (lane == 0) {
#pragma unroll
        for (int i = 0; i < 16; ++i) g_coef[(NQUAD + i) * KC + w] = bv[i];
        g_const[w] = logf(pi[w]) - 0.5f * logdet - 8.0f * 1.8378770664093453f - 0.5f * muPmu;
    }
}

// ---------------------------------------------------------------------------
// softmax + float4 store for one point's 16 logits
// ---------------------------------------------------------------------------
__device__ __forceinline__ void softmax_store(const float* l, float* outp) {
    float mx = l[0];
#pragma unroll
    for (int k = 1; k < 16; ++k) mx = fmaxf(mx, l[k]);
    float e[16], s = 0.0f;
#pragma unroll
    for (int k = 0; k < 16; ++k) { e[k] = __expf(l[k] - mx); s += e[k]; }
    float r = __fdividef(1.0f, s);
    float4* o = reinterpret_cast<float4*>(outp);
    o[0] = make_float4(e[0] * r,  e[1] * r,  e[2] * r,  e[3] * r);
    o[1] = make_float4(e[4] * r,  e[5] * r,  e[6] * r,  e[7] * r);
    o[2] = make_float4(e[8] * r,  e[9] * r,  e[10] * r, e[11] * r);
    o[3] = make_float4(e[12] * r, e[13] * r, e[14] * r, e[15] * r);
}

// ---------------------------------------------------------------------------
// Per-feature inner body: duplicate scalar feature values (ALU movs, off the
// FMA pipe) and run 16 f2fma against plain-float cluster-contiguous coefs
// (4 LDS.128 per feature, warp-uniform -> 1 wavefront each).
// ---------------------------------------------------------------------------
__device__ __forceinline__ void accum_feature(float pA, float pB,
                                              const float* cf,
                                              unsigned long long* accA,
                                              unsigned long long* accB) {
    unsigned long long fA = f2dup(pA);
    unsigned long long fB = f2dup(pB);
    const ulonglong2* cp = reinterpret_cast<const ulonglong2*>(cf);
#pragma unroll
    for (int m = 0; m < 4; ++m) {
        ulonglong2 cc = cp[m];                 // clusters 4m..4m+3 (two packed pairs)
        accA[2 * m]     = f2fma(cc.x, fA, accA[2 * m]);
        accA[2 * m + 1] = f2fma(cc.y, fA, accA[2 * m + 1]);
        accB[2 * m]     = f2fma(cc.x, fB, accB[2 * m]);
        accB[2 * m + 1] = f2fma(cc.y, fB, accB[2 * m + 1]);
    }
}

// ---------------------------------------------------------------------------
// Main kernel: 2 points/thread, scalar X (32 regs), cluster-packed acc
// (32 regs). Architectural state ~64 regs -> 3 CTAs/SM at 256 threads.
// ---------------------------------------------------------------------------
__global__ void __launch_bounds__(256, 3) gmm_main(const float* __restrict__ x,
                                                   float* __restrict__ out, int n) {
    __shared__ __align__(16) float s_coef[NFEAT * KC];   // [feature][cluster]
    __shared__ __align__(16) float s_const[KC];

    for (int idx = threadIdx.x; idx < NFEAT * KC; idx += blockDim.x)
        s_coef[idx] = g_coef[idx];
    if (threadIdx.x < KC) s_const[threadIdx.x] = g_const[threadIdx.x];
    __syncthreads();

    long long t  = (long long)blockIdx.x * blockDim.x + threadIdx.x;
    long long n0 = 2 * t;
    if (n0 >= n) return;
    const bool hasB = (n0 + 1 < n);

    const float4* x4A = reinterpret_cast<const float4*>(x + n0 * DD);
    const float4* x4B = reinterpret_cast<const float4*>(x + (hasB ? (n0 + 1) : n0) * DD);

    float xA[16], xB[16];
#pragma unroll
    for (int q = 0; q < 4; ++q) {
        float4 va = x4A[q], vb = x4B[q];
        xA[4 * q + 0] = va.x; xA[4 * q + 1] = va.y; xA[4 * q + 2] = va.z; xA[4 * q + 3] = va.w;
        xB[4 * q + 0] = vb.x; xB[4 * q + 1] = vb.y; xB[4 * q + 2] = vb.z; xB[4 * q + 3] = vb.w;
    }

    unsigned long long accA[8], accB[8];
    {
        const unsigned long long* cu = reinterpret_cast<const unsigned long long*>(s_const);
#pragma unroll
        for (int m = 0; m < 8; ++m) { accA[m] = cu[m]; accB[m] = cu[m]; }
    }

    // quadratic features (i<=j), feature p = j*(j+1)/2 + i
    int p = 0;
#pragma unroll
    for (int j = 0; j < 16; ++j) {
#pragma unroll
        for (int i = 0; i <= j; ++i) {
            accum_feature(xA[i] * xA[j], xB[i] * xB[j], s_coef + p * KC, accA, accB);
            ++p;
        }
    }
    // linear features
#pragma unroll
    for (int i = 0; i < 16; ++i)
        accum_feature(xA[i], xB[i], s_coef + (NQUAD + i) * KC, accA, accB);

    // unpack logits (reuse xA/xB storage as logits)
    float la[16], lb[16];
#pragma unroll
    for (int m = 0; m < 8; ++m) {
        f2unpack(accA[m], la[2 * m], la[2 * m + 1]);
        f2unpack(accB[m], lb[2 * m], lb[2 * m + 1]);
    }

    softmax_store(la, out + n0 * KC);
    if (hasB) softmax_store(lb, out + (n0 + 1) * KC);
}

extern "C" void kernel_launch(void* const* d_in, const int* in_sizes, int n_in,
                              void* d_out, int out_size) {
    const float* x     = (const float*)d_in[0];
    const float* pi    = (const float*)d_in[1];
    const float* mu    = (const float*)d_in[2];
    const float* Sigma = (const float*)d_in[3];
    float* out = (float*)d_out;

    int n = in_sizes[0] / DD;

    gmm_precompute<<<1, 512>>>(pi, mu, Sigma);

    int nthreads = (n + 1) / 2;   // 2 points per thread
    int block = 256;
    int grid  = (nthreads + block - 1) / block;
    gmm_main<<<grid, block>>>(x, out, n);
}